// round 15
// baseline (speedup 1.0000x reference)
#include <cuda_runtime.h>
#include <cuda_bf16.h>
#include <math.h>
#include <stdint.h>

#define BATCHN 2
#define SEQL   4096
#define DMODEL 1024
#define NH     16
#define HD     64
#define CHUNKL 64
#define NCH    64
#define CONVD  3072
#define DINP   3088
#define BHN    (BATCHN*NH)
#define BSN    (BATCHN*SEQL)
#define K3     3072
#define K2     2048
#define NPAD_IP 3200
#define NPERS  296

// ---------------- scratch ------------------------------------------------------
__device__ float g_xw[(size_t)BSN*DINP];
__device__ float g_Cm[(size_t)BHN*SEQL*HD];
__device__ float g_cumA[(size_t)BHN*SEQL];
__device__ float g_states[(size_t)BHN*NCH*HD*HD];
__device__ float g_nstates[(size_t)BHN*NCH*HD*HD];
__device__ float g_Atot[BHN*NCH];
__device__ float g_ndec[BHN*NCH];
__device__ float g_nnew[BHN*NCH];
__device__ float g_Ydiag[(size_t)BHN*SEQL*HD];
__device__ float g_ndiag[(size_t)BHN*SEQL];
__device__ __nv_bfloat16 g_xs[(size_t)BSN*K2];
__device__ __nv_bfloat16 g_ws[(size_t)NPAD_IP*K2];
__device__ __nv_bfloat16 g_w2s[(size_t)DMODEL*K2];
__device__ __nv_bfloat16 g_ys[(size_t)BSN*K2];

// ---------------- helpers ------------------------------------------------------
__device__ __forceinline__ uint32_t smem_u32(const void* p) {
    uint32_t a;
    asm("{ .reg .u64 t; cvta.to.shared.u64 t, %1; cvt.u32.u64 %0, t; }" : "=r"(a) : "l"(p));
    return a;
}
#define CP16(dst, src)  asm volatile("cp.async.cg.shared.global [%0], [%1], 16;" :: "r"(dst), "l"(src) : "memory")
#define CP_COMMIT()     asm volatile("cp.async.commit_group;" ::: "memory")

__device__ __forceinline__ void ldm_x4(uint32_t* r, uint32_t addr) {
    asm volatile("ldmatrix.sync.aligned.m8n8.x4.shared.b16 {%0,%1,%2,%3}, [%4];"
        : "=r"(r[0]), "=r"(r[1]), "=r"(r[2]), "=r"(r[3]) : "r"(addr));
}
__device__ __forceinline__ void mma_bf16(float* c, const uint32_t* a, const uint32_t* b) {
    asm volatile("mma.sync.aligned.m16n8k16.row.col.f32.bf16.bf16.f32 "
        "{%0,%1,%2,%3},{%4,%5,%6,%7},{%8,%9},{%0,%1,%2,%3};"
        : "+f"(c[0]), "+f"(c[1]), "+f"(c[2]), "+f"(c[3])
        : "r"(a[0]), "r"(a[1]), "r"(a[2]), "r"(a[3]), "r"(b[0]), "r"(b[1]));
}

// ---------------- persistent bf16 HMMA GEMM, continuous cp.async ring -------------
#define BK    64
#define ROWE  72
#define NSTG  3
#define STGB  (2u * 128 * ROWE * 2)
#define OPB   (128u * ROWE * 2)

__global__ __launch_bounds__(256, 2) void mma_gemm_k(
    const __nv_bfloat16* __restrict__ A, const __nv_bfloat16* __restrict__ B,
    float* __restrict__ C, int K, int Nout, int ldc, int aW, int bW,
    int tilesX, int nTiles)
{
    extern __shared__ __align__(16) __nv_bfloat16 dsm[];

    const int tid  = threadIdx.x;
    const int lane = tid & 31;
    const int wid  = tid >> 5;
    const int wm   = wid & 1;
    const int wn   = wid >> 1;
    const int nk   = K / BK;

    const int r0 = tid >> 3;
    const int c0 = (tid & 7) * 8;
    uint32_t sbase = smem_u32(dsm);

    uint32_t aoff[4];
#pragma unroll
    for (int mi = 0; mi < 4; mi++) {
        int row = wm * 64 + mi * 16 + (lane & 15);
        aoff[mi] = (uint32_t)(row * ROWE + (lane >> 4) * 8) * 2;
    }
    uint32_t boffp[2];
#pragma unroll
    for (int pi = 0; pi < 2; pi++) {
        int l2  = lane & 15;
        int grp = lane >> 4;
        int row = wn * 32 + (pi * 2 + grp) * 8 + (l2 & 7);
        boffp[pi] = (uint32_t)(row * ROWE + ((l2 >> 3) & 1) * 8) * 2;
    }

    int tile = blockIdx.x;
    int bm = (tile / tilesX) * 128;
    int bn = (tile % tilesX) * 128;

    // lookahead load cursor
    int jtile = tile, jkt = 0;
    int bmj = bm, bnj = bn;
    bool jv = true;

    // prologue: 2 iterations into stages 0,1
#pragma unroll
    for (int p = 0; p < 2; p++) {
        if (jv) {
            uint32_t sa = sbase + (uint32_t)p * STGB, sb = sa + OPB;
            int k0 = jkt * BK;
            int kA = (k0 < aW) ? k0 : k0 - aW;
            int kB = (k0 < bW) ? k0 : k0 - bW;
#pragma unroll
            for (int i = 0; i < 4; i++) {
                int r = r0 + i * 32;
                CP16(sa + (uint32_t)(r * ROWE + c0) * 2, A + (size_t)(bmj + r) * K2 + kA + c0);
                CP16(sb + (uint32_t)(r * ROWE + c0) * 2, B + (size_t)(bnj + r) * K2 + kB + c0);
            }
        }
        CP_COMMIT();
        if (++jkt == nk) {
            jkt = 0; jtile += NPERS; jv = (jtile < nTiles);
            if (jv) { bmj = (jtile / tilesX) * 128; bnj = (jtile % tilesX) * 128; }
        }
    }

    float acc[4][4][4];
#pragma unroll
    for (int i = 0; i < 4; i++)
#pragma unroll
        for (int j = 0; j < 4; j++)
#pragma unroll
            for (int e = 0; e < 4; e++) acc[i][j][e] = 0.f;

    int st = 0, ldst = 2, kt = 0;
#pragma unroll 1
    while (tile < nTiles) {
        asm volatile("cp.async.wait_group 1;" ::: "memory");
        __syncthreads();

        // issue lookahead loads
        if (jv) {
            uint32_t sa = sbase + (uint32_t)ldst * STGB, sb = sa + OPB;
            int k0 = jkt * BK;
            int kA = (k0 < aW) ? k0 : k0 - aW;
            int kB = (k0 < bW) ? k0 : k0 - bW;
#pragma unroll
            for (int i = 0; i < 4; i++) {
                int r = r0 + i * 32;
                CP16(sa + (uint32_t)(r * ROWE + c0) * 2, A + (size_t)(bmj + r) * K2 + kA + c0);
                CP16(sb + (uint32_t)(r * ROWE + c0) * 2, B + (size_t)(bnj + r) * K2 + kB + c0);
            }
        }
        CP_COMMIT();
        if (++jkt == nk) {
            jkt = 0; jtile += NPERS; jv = (jtile < nTiles);
            if (jv) { bmj = (jtile / tilesX) * 128; bnj = (jtile % tilesX) * 128; }
        }
        if (++ldst == 3) ldst = 0;

        // consume stage st
        {
            uint32_t sa = sbase + (uint32_t)st * STGB, sb = sa + OPB;
#pragma unroll
            for (int ksp = 0; ksp < 2; ksp++) {
                uint32_t a[2][4][4];
                uint32_t bp[2][2][4];
#pragma unroll
                for (int k2 = 0; k2 < 2; k2++) {
                    uint32_t kadd = (uint32_t)((ksp * 2 + k2) * 16) * 2;
#pragma unroll
                    for (int mi = 0; mi < 4; mi++) ldm_x4(a[k2][mi], sa + aoff[mi] + kadd);
#pragma unroll
                    for (int pi = 0; pi < 2; pi++) ldm_x4(bp[k2][pi], sb + boffp[pi] + kadd);
                }
#pragma unroll
                for (int k2 = 0; k2 < 2; k2++)
#pragma unroll
                    for (int mi = 0; mi < 4; mi++)
#pragma unroll
                        for (int ni = 0; ni < 4; ni++)
                            mma_bf16(acc[mi][ni], a[k2][mi], &bp[k2][ni >> 1][(ni & 1) * 2]);
            }
        }
        if (++st == 3) st = 0;

        if (++kt == nk) {
            // epilogue for current tile
#pragma unroll
            for (int mi = 0; mi < 4; mi++) {
                int row = bm + wm * 64 + mi * 16 + (lane >> 2);
#pragma unroll
                for (int ni = 0; ni < 4; ni++) {
                    int col = bn + wn * 32 + ni * 8 + (lane & 3) * 2;
                    if (col < Nout) {
                        *(float2*)(C + (size_t)row * ldc + col)       = make_float2(acc[mi][ni][0], acc[mi][ni][1]);
                        *(float2*)(C + (size_t)(row + 8) * ldc + col) = make_float2(acc[mi][ni][2], acc[mi][ni][3]);
                    }
                }
            }
#pragma unroll
            for (int i = 0; i < 4; i++)
#pragma unroll
                for (int j = 0; j < 4; j++)
#pragma unroll
                    for (int e = 0; e < 4; e++) acc[i][j][e] = 0.f;
            kt = 0;
            tile += NPERS;
            if (tile < nTiles) {
                bm = (tile / tilesX) * 128;
                bn = (tile % tilesX) * 128;
            }
        }
    }
}

// ---------------- merged fp32 -> bf16 hi/lo splits ([hi,lo] layout) ----------------
#define NSPLIT_A (BSN*DMODEL)
#define NSPLIT_B (NPAD_IP*DMODEL)
#define NSPLIT_C (DMODEL*DMODEL)

__global__ void split_all_k(const float* __restrict__ x, const float* __restrict__ ipw,
                            const float* __restrict__ opw)
{
    int gi = blockIdx.x * blockDim.x + threadIdx.x;
    const float* src;
    __nv_bfloat16* dst;
    int rows, idx;
    if (gi < NSPLIT_A) {
        src = x; dst = g_xs; rows = BSN; idx = gi;
    } else if (gi < NSPLIT_A + NSPLIT_B) {
        src = ipw; dst = g_ws; rows = DINP; idx = gi - NSPLIT_A;
    } else if (gi < NSPLIT_A + NSPLIT_B + NSPLIT_C) {
        src = opw; dst = g_w2s; rows = DMODEL; idx = gi - NSPLIT_A - NSPLIT_B;
    } else return;
    int r = idx / DMODEL, k = idx % DMODEL;
    float v = (r < rows) ? src[(size_t)r * DMODEL + k] : 0.f;
    __nv_bfloat16 hi = __float2bfloat16(v);
    __nv_bfloat16 lo = __float2bfloat16(v - __bfloat162float(hi));
    size_t b = (size_t)r * K2 + k;
    dst[b] = hi;
    dst[b + DMODEL] = lo;
}

// --------------- fused conv + per-chunk tile kernel (3 smem arrays, occ 4) ---------
#define RP 68

__global__ __launch_bounds__(256, 4) void chunk_k(const float* __restrict__ cw,
                                                  const float* __restrict__ cb,
                                                  const float* __restrict__ w_base)
{
    extern __shared__ float sh[];
    float (*sCT)[RP] = (float(*)[RP])sh;
    float (*sBT)[RP] = (float(*)[RP])(sh + 64 * RP);
    float (*sX)[RP]  = (float(*)[RP])(sh + 2 * 64 * RP);
    float (*sGL)[RP] = sCT;
    __shared__ float scum[64];
    __shared__ float smn[64];
    __shared__ float sds[64];

    int bh = blockIdx.x >> 6;
    int c  = blockIdx.x & 63;
    int b  = bh >> 4;
    int h  = bh & 15;
    int tid = threadIdx.x;
    size_t base = ((size_t)bh * SEQL + (size_t)c * CHUNKL) * HD;
    size_t abase = (size_t)bh * SEQL + c * 64;

    if (tid < 192) {
        int n = tid & 63;
        int sect = tid >> 6;
        int ch = sect * 1024 + h * 64 + n;
        float w0 = cw[ch * 4 + 0], w1 = cw[ch * 4 + 1];
        float w2 = cw[ch * 4 + 2], w3 = cw[ch * 4 + 3];
        float bias = cb[ch];
        size_t rowbase = ((size_t)b * SEQL + (size_t)c * 64) * DINP + ch;

        float h0 = 0.f, h1 = 0.f, h2 = 0.f;
        if (c > 0) {
            h0 = g_xw[rowbase - 3 * (size_t)DINP];
            h1 = g_xw[rowbase - 2 * (size_t)DINP];
            h2 = g_xw[rowbase - 1 * (size_t)DINP];
        }
#pragma unroll 1
        for (int l0 = 0; l0 < 64; l0 += 8) {
            float xv[8];
#pragma unroll
            for (int k = 0; k < 8; k++)
                xv[k] = g_xw[rowbase + (size_t)(l0 + k) * DINP];
#pragma unroll
            for (int k = 0; k < 8; k++) {
                float o = fmaf(h0, w0, fmaf(h1, w1, fmaf(h2, w2, fmaf(xv[k], w3, bias))));
                int l = l0 + k;
                if (sect == 0) {
                    sCT[n][l] = o;
                    g_Cm[base + (size_t)l * 64 + n] = o;
                } else if (sect == 1) {
                    sBT[n][l] = o;
                } else {
                    sX[l][n] = o;
                }
                h0 = h1; h1 = h2; h2 = xv[k];
            }
        }
    } else if (tid < 224) {
        int lane = tid & 31;
        float wbh = w_base[h];
        float v0 = g_xw[(size_t)(b * SEQL + c * 64 + 2 * lane)     * DINP + CONVD + h] * wbh;
        float v1 = g_xw[(size_t)(b * SEQL + c * 64 + 2 * lane + 1) * DINP + CONVD + h] * wbh;
        float s = v0 + v1;
#pragma unroll
        for (int o = 1; o < 32; o <<= 1) {
            float t = __shfl_up_sync(0xffffffffu, s, o);
            if (lane >= o) s += t;
        }
        float c1 = s, cc0 = s - v1;
        scum[2 * lane] = cc0; scum[2 * lane + 1] = c1;
        g_cumA[abase + 2 * lane] = cc0;
        g_cumA[abase + 2 * lane + 1] = c1;
        float mm = fminf(cc0, c1);
#pragma unroll
        for (int o = 1; o < 32; o <<= 1) {
            float t = __shfl_up_sync(0xffffffffu, mm, o);
            if (lane >= o) mm = fminf(mm, t);
        }
        float prev = __shfl_up_sync(0xffffffffu, mm, 1);
        if (lane == 0) prev = 1e30f;
        smn[2 * lane]     = fminf(prev, cc0);
        smn[2 * lane + 1] = fminf(prev, fminf(cc0, c1));
        float mtot = __shfl_sync(0xffffffffu, mm, 31);
        float d0 = __expf(mtot - cc0), d1 = __expf(mtot - c1);
        sds[2 * lane] = d0; sds[2 * lane + 1] = d1;
        float nd = d0 + d1;
#pragma unroll
        for (int o = 16; o; o >>= 1) nd += __shfl_xor_sync(0xffffffffu, nd, o);
        float ctot = __shfl_sync(0xffffffffu, c1, 31);
        if (lane == 0) { g_Atot[bh * NCH + c] = ctot; g_ndec[bh * NCH + c] = nd; }
    }
    __syncthreads();

    int tj = (tid & 15) * 4;
    int ti = (tid >> 4) * 4;

    float gl4[4][4];
    float nsum[4] = {0.f, 0.f, 0.f, 0.f};
    {
        float r[4][4];
#pragma unroll
        for (int a = 0; a < 4; a++)
#pragma unroll
            for (int b2 = 0; b2 < 4; b2++) r[a][b2] = 0.f;
#pragma unroll 4
        for (int n = 0; n < 64; n++) {
            float4 cv = *(const float4*)&sCT[n][ti];
            float4 bv = *(const float4*)&sBT[n][tj];
            float cva[4] = {cv.x, cv.y, cv.z, cv.w};
            float bva[4] = {bv.x, bv.y, bv.z, bv.w};
#pragma unroll
            for (int a = 0; a < 4; a++)
#pragma unroll
                for (int b2 = 0; b2 < 4; b2++) r[a][b2] = fmaf(cva[a], bva[b2], r[a][b2]);
        }
#pragma unroll
        for (int a = 0; a < 4; a++) {
            int i = ti + a;
            float m = smn[i];
#pragma unroll
            for (int b2 = 0; b2 < 4; b2++) {
                float e = __expf(m - scum[tj + b2]);
                bool in = (tj + b2 <= i);
                gl4[a][b2] = in ? r[a][b2] * e : 0.f;
                nsum[a] += in ? e : 0.f;
            }
        }
    }
#pragma unroll
    for (int a = 0; a < 4; a++) {
#pragma unroll
        for (int o = 8; o; o >>= 1)
            nsum[a] += __shfl_xor_sync(0xffffffffu, nsum[a], o);
    }
    if ((tid & 15) == 0) {
#pragma unroll
        for (int a = 0; a < 4; a++)
            g_ndiag[abase + ti + a] = nsum[a];
    }
    __syncthreads();

#pragma unroll
    for (int a = 0; a < 4; a++)
        *(float4*)&sGL[ti + a][tj] = make_float4(gl4[a][0], gl4[a][1], gl4[a][2], gl4[a][3]);
    __syncthreads();

    {
        float r[4][4];
#pragma unroll
        for (int a = 0; a < 4; a++)
#pragma unroll
            for (int b2 = 0; b2 < 4; b2++) r[a][b2] = 0.f;
#pragma unroll 4
        for (int j = 0; j < 64; j++) {
            float4 xv = *(const float4*)&sX[j][tj];
            float xva[4] = {xv.x, xv.y, xv.z, xv.w};
            float gl[4];
#pragma unroll
            for (int a = 0; a < 4; a++) gl[a] = sGL[ti + a][j];
#pragma unroll
            for (int a = 0; a < 4; a++)
#pragma unroll
                for (int b2 = 0; b2 < 4; b2++) r[a][b2] = fmaf(gl[a], xva[b2], r[a][b2]);
        }
#pragma unroll
        for (int a = 0; a < 4; a++)
            *(float4*)(g_Ydiag + base + (size_t)(ti + a) * 64 + tj)
                = make_float4(r[a][0], r[a][1], r[a][2], r[a][3]);
    }
    {
        float r[4][4];
#pragma unroll
        for (int a = 0; a < 4; a++)
#pragma unroll
            for (int b2 = 0; b2 < 4; b2++) r[a][b2] = 0.f;
#pragma unroll 4
        for (int l = 0; l < 64; l++) {
            float d = sds[l];
            float4 xv = *(const float4*)&sX[l][tj];
            float xva[4] = {xv.x * d, xv.y * d, xv.z * d, xv.w * d};
            float bva[4];
#pragma unroll
            for (int a = 0; a < 4; a++) bva[a] = sBT[ti + a][l];
#pragma unroll
            for (int a = 0; a < 4; a++)
#pragma unroll
                for (int b2 = 0; b2 < 4; b2++) r[a][b2] = fmaf(bva[a], xva[b2], r[a][b2]);
        }
        size_t sb = ((size_t)bh * NCH + c) * 4096;
#pragma unroll
        for (int a = 0; a < 4; a++)
            *(float4*)(g_states + sb + (size_t)(ti + a) * 64 + tj)
                = make_float4(r[a][0], r[a][1], r[a][2], r[a][3]);
    }
}

// --------------- chunk recurrence scan: coefficient-hoisted, 512 blocks ------------
__global__ __launch_bounds__(256) void scan_k()
{
    __shared__ float sf[64];
    __shared__ float sg[64];
    __shared__ float snd[64];

    int bh   = blockIdx.x >> 4;
    int part = blockIdx.x & 15;
    int tid  = threadIdx.x;
    int e0   = part * 256 + tid;
    size_t sb = (size_t)bh * NCH * 4096;

    if (tid < 32) {
        int lane = tid;
        float a0 = (2 * lane < 63)     ? g_Atot[bh * NCH + 2 * lane]     : 0.f;
        float a1 = (2 * lane + 1 < 63) ? g_Atot[bh * NCH + 2 * lane + 1] : 0.f;
        float s = a0 + a1;
#pragma unroll
        for (int o = 1; o < 32; o <<= 1) {
            float t = __shfl_up_sync(0xffffffffu, s, o);
            if (lane >= o) s += t;
        }
        float cc1 = s, cc0 = s - a1;
        float mm = fminf(cc0, cc1);
#pragma unroll
        for (int o = 1; o < 32; o <<= 1) {
            float t = __shfl_up_sync(0xffffffffu, mm, o);
            if (lane >= o) mm = fminf(mm, t);
        }
        float prevmm = __shfl_up_sync(0xffffffffu, mm, 1);
        if (lane == 0) prevmm = 0.f;
        prevmm = fminf(prevmm, 0.f);
        float m0 = fminf(prevmm, cc0);
        float m1 = fminf(m0, cc1);
        sf[2 * lane]     = __expf(m0 - prevmm);
        sf[2 * lane + 1] = __expf(m1 - m0);
        sg[2 * lane]     = __expf(m0 - cc0);
        sg[2 * lane + 1] = __expf(m1 - cc1);
        snd[2 * lane]     = (2 * lane < 63)     ? g_ndec[bh * NCH + 2 * lane]     : 0.f;
        snd[2 * lane + 1] = (2 * lane + 1 < 63) ? g_ndec[bh * NCH + 2 * lane + 1] : 0.f;
    }
    __syncthreads();

    if (part == 0 && tid == 32) {
        float nacc = 0.f;
        g_nnew[bh * NCH] = 0.f;
#pragma unroll 1
        for (int z = 0; z < 63; z++) {
            nacc = nacc * sf[z] + sg[z] * snd[z];
            g_nnew[bh * NCH + z + 1] = nacc;
        }
    }

    float pf[4];
#pragma unroll
    for (int z = 0; z < 4; z++) pf[z] = g_states[sb + (size_t)z * 4096 + e0];

    float r = 0.f;
    g_nstates[sb + e0] = 0.f;
#pragma unroll 1
    for (int z = 0; z < 63; z++) {
        float s = pf[z & 3];
        if (z + 4 < 63) pf[z & 3] = g_states[sb + (size_t)(z + 4) * 4096 + e0];
        r = r * sf[z] + sg[z] * s;
        g_nstates[sb + (size_t)(z + 1) * 4096 + e0] = r;
    }
}

// --------------- Y_off + combine + normalize + bf16 split (hi,lo layout) ----------
__global__ __launch_bounds__(256) void yoff_k()
{
    __shared__ float sCT[64][RP];
    __shared__ float sST[64][RP];
    __shared__ float scum[64];
    __shared__ float sdo[64];

    int bh = blockIdx.x >> 6;
    int c  = blockIdx.x & 63;
    int b  = bh >> 4;
    int h  = bh & 15;
    int tid = threadIdx.x;
    size_t baseC = ((size_t)bh * SEQL + (size_t)c * 64) * HD;
    size_t baseS = ((size_t)bh * NCH + c) * 4096;

    {
        const float4* pC = (const float4*)(g_Cm + baseC);
        const float4* pS = (const float4*)(g_nstates + baseS);
        for (int i4 = tid; i4 < 1024; i4 += 256) {
            int l = i4 >> 4, n4 = (i4 & 15) * 4;
            float4 v = pC[i4];
            sCT[n4][l] = v.x; sCT[n4+1][l] = v.y; sCT[n4+2][l] = v.z; sCT[n4+3][l] = v.w;
            v = pS[i4];
            *(float4*)&sST[l][n4] = v;
        }
    }
    if (tid < 32) {
        float a0 = g_cumA[(size_t)bh * SEQL + c * 64 + 2 * tid];
        float a1 = g_cumA[(size_t)bh * SEQL + c * 64 + 2 * tid + 1];
        scum[2 * tid] = a0; scum[2 * tid + 1] = a1;
        float mx = fmaxf(a0, a1);
#pragma unroll
        for (int o = 16; o; o >>= 1) mx = fmaxf(mx, __shfl_xor_sync(0xffffffffu, mx, o));
        sdo[2 * tid]     = __expf(a0 - mx);
        sdo[2 * tid + 1] = __expf(a1 - mx);
    }
    __syncthreads();

    float nn = g_nnew[bh * NCH + c];
    int tl = (tid >> 4) * 4;
    int tp = (tid & 15) * 4;
    float r[4][4];
#pragma unroll
    for (int a = 0; a < 4; a++)
#pragma unroll
        for (int b2 = 0; b2 < 4; b2++) r[a][b2] = 0.f;
#pragma unroll 4
    for (int n = 0; n < 64; n++) {
        float4 cv = *(const float4*)&sCT[n][tl];
        float4 sv = *(const float4*)&sST[n][tp];
        float cva[4] = {cv.x, cv.y, cv.z, cv.w};
        float sva[4] = {sv.x, sv.y, sv.z, sv.w};
#pragma unroll
        for (int a = 0; a < 4; a++)
#pragma unroll
            for (int b2 = 0; b2 < 4; b2++) r[a][b2] = fmaf(cva[a], sva[b2], r[a][b2]);
    }
#pragma unroll
    for (int a = 0; a < 4; a++) {
        int l = tl + a;
        float d = sdo[l];
        float nm = g_ndiag[(size_t)bh * SEQL + c * 64 + l] + nn * d;
        float inv = 1.f / nm;
        int s = c * 64 + l;
        size_t rowb = ((size_t)b * SEQL + s) * K2 + h * 64;
        const float4 yv = *(const float4*)(g_Ydiag + baseC + (size_t)l * 64 + tp);
        float v0 = (yv.x + d * r[a][0]) * inv;
        float v1 = (yv.y + d * r[a][1]) * inv;
        float v2 = (yv.z + d * r[a][2]) * inv;
        float v3 = (yv.w + d * r[a][3]) * inv;
        __nv_bfloat16 h0 = __float2bfloat16(v0), h1 = __float2bfloat16(v1);
        __nv_bfloat16 h2 = __float2bfloat16(v2), h3 = __float2bfloat16(v3);
        __nv_bfloat16 l0 = __float2bfloat16(v0 - __bfloat162float(h0));
        __nv_bfloat16 l1 = __float2bfloat16(v1 - __bfloat162float(h1));
        __nv_bfloat16 l2 = __float2bfloat16(v2 - __bfloat162float(h2));
        __nv_bfloat16 l3 = __float2bfloat16(v3 - __bfloat162float(h3));
        __nv_bfloat162 hp0 = __halves2bfloat162(h0, h1), hp1 = __halves2bfloat162(h2, h3);
        __nv_bfloat162 lp0 = __halves2bfloat162(l0, l1), lp1 = __halves2bfloat162(l2, l3);
        uint2 hu, lu;
        hu.x = *(uint32_t*)&hp0; hu.y = *(uint32_t*)&hp1;
        lu.x = *(uint32_t*)&lp0; lu.y = *(uint32_t*)&lp1;
        *(uint2*)(g_ys + rowb + tp)          = hu;
        *(uint2*)(g_ys + rowb + tp + DMODEL) = lu;
    }
}

// ------------------------------- launch ---------------------------------------------
extern "C" void kernel_launch(void* const* d_in, const int* in_sizes, int n_in,
                              void* d_out, int out_size)
{
    const float* x   = (const float*)d_in[0];
    const float* ipw = (const float*)d_in[1];
    const float* cw  = (const float*)d_in[2];
    const float* cb  = (const float*)d_in[3];
    const float* wb  = (const float*)d_in[4];
    const float* opw = (const float*)d_in[5];
    float* out = (float*)d_out;

    float *p_xw = nullptr;
    __nv_bfloat16 *p_xs, *p_ws, *p_w2s, *p_ys;
    cudaGetSymbolAddress((void**)&p_xw, g_xw);
    cudaGetSymbolAddress((void**)&p_xs, g_xs);
    cudaGetSymbolAddress((void**)&p_ws, g_ws);
    cudaGetSymbolAddress((void**)&p_w2s, g_w2s);
    cudaGetSymbolAddress((void**)&p_ys, g_ys);

    const int SMEM_CHUNK = 3 * 64 * RP * 4;
    cudaFuncSetAttribute(chunk_k, cudaFuncAttributeMaxDynamicSharedMemorySize, SMEM_CHUNK);
    const int SMEM_GEMM = NSTG * (int)STGB;
    cudaFuncSetAttribute(mma_gemm_k, cudaFuncAttributeMaxDynamicSharedMemorySize, SMEM_GEMM);

    // 0) merged bf16 splits
    {
        int total = NSPLIT_A + NSPLIT_B + NSPLIT_C;
        split_all_k<<<(total + 255) / 256, 256>>>(x, ipw, opw);
    }

    // 1) in_proj via persistent HMMA
    mma_gemm_k<<<NPERS, 256, SMEM_GEMM>>>(p_xs, p_ws, p_xw, K3, DINP, DINP, 1024, 2048,
                                          NPAD_IP / 128, (NPAD_IP / 128) * (BSN / 128));

    // 2) fused conv + per-chunk tiles
    chunk_k<<<BHN * NCH, 256, SMEM_CHUNK>>>(cw, cb, wb);

    // 3) chunk recurrence scan
    scan_k<<<BHN * 16, 256>>>();

    // 4) off-diagonal + normalize + fused bf16 split
    yoff_k<<<BHN * NCH, 256>>>();

    // 5) out_proj via persistent HMMA
    mma_gemm_k<<<NPERS, 256, SMEM_GEMM>>>(p_ys, p_w2s, out, K3, DMODEL, DMODEL, 1024, 2048,
                                          DMODEL / 128, (DMODEL / 128) * (BSN / 128));
}

// round 16
// speedup vs baseline: 1.1111x; 1.1111x over previous
#include <cuda_runtime.h>
#include <cuda_bf16.h>
#include <math.h>
#include <stdint.h>

#define BATCHN 2
#define SEQL   4096
#define DMODEL 1024
#define NH     16
#define HD     64
#define CHUNKL 64
#define NCH    64
#define CONVD  3072
#define DINP   3088
#define BHN    (BATCHN*NH)
#define BSN    (BATCHN*SEQL)
#define K3     3072
#define K2     2048
#define NPAD_IP 3200

// ---------------- scratch ------------------------------------------------------
__device__ float g_xw[(size_t)BSN*DINP];
__device__ float g_Cm[(size_t)BHN*SEQL*HD];
__device__ float g_cumA[(size_t)BHN*SEQL];
__device__ float g_states[(size_t)BHN*NCH*HD*HD];
__device__ float g_nstates[(size_t)BHN*NCH*HD*HD];
__device__ float g_Atot[BHN*NCH];
__device__ float g_ndec[BHN*NCH];
__device__ float g_nnew[BHN*NCH];
__device__ float g_Ydiag[(size_t)BHN*SEQL*HD];
__device__ float g_ndiag[(size_t)BHN*SEQL];
__device__ __nv_bfloat16 g_xs[(size_t)BSN*K2];
__device__ __nv_bfloat16 g_ws[(size_t)NPAD_IP*K2];
__device__ __nv_bfloat16 g_w2s[(size_t)DMODEL*K2];
__device__ __nv_bfloat16 g_ys[(size_t)BSN*K2];

// ---------------- helpers ------------------------------------------------------
__device__ __forceinline__ uint32_t smem_u32(const void* p) {
    uint32_t a;
    asm("{ .reg .u64 t; cvta.to.shared.u64 t, %1; cvt.u32.u64 %0, t; }" : "=r"(a) : "l"(p));
    return a;
}
#define CP16(dst, src)  asm volatile("cp.async.cg.shared.global [%0], [%1], 16;" :: "r"(dst), "l"(src) : "memory")
#define CP_COMMIT()     asm volatile("cp.async.commit_group;" ::: "memory")

__device__ __forceinline__ void ldm_x4(uint32_t* r, uint32_t addr) {
    asm volatile("ldmatrix.sync.aligned.m8n8.x4.shared.b16 {%0,%1,%2,%3}, [%4];"
        : "=r"(r[0]), "=r"(r[1]), "=r"(r[2]), "=r"(r[3]) : "r"(addr));
}
__device__ __forceinline__ void mma_bf16(float* c, const uint32_t* a, const uint32_t* b) {
    asm volatile("mma.sync.aligned.m16n8k16.row.col.f32.bf16.bf16.f32 "
        "{%0,%1,%2,%3},{%4,%5,%6,%7},{%8,%9},{%0,%1,%2,%3};"
        : "+f"(c[0]), "+f"(c[1]), "+f"(c[2]), "+f"(c[3])
        : "r"(a[0]), "r"(a[1]), "r"(a[2]), "r"(a[3]), "r"(b[0]), "r"(b[1]));
}

// ---------------- bf16 HMMA GEMM (BK=64, 3 stages, k-aliased operands) -----------
#define BK    64
#define ROWE  72
#define NSTG  3
#define STGB  (2u * 128 * ROWE * 2)
#define OPB   (128u * ROWE * 2)

__global__ __launch_bounds__(256, 2) void mma_gemm_k(
    const __nv_bfloat16* __restrict__ A, const __nv_bfloat16* __restrict__ B,
    float* __restrict__ C, int K, int Nout, int ldc, int aW, int bW)
{
    extern __shared__ __align__(16) __nv_bfloat16 dsm[];

    const int tid  = threadIdx.x;
    const int lane = tid & 31;
    const int wid  = tid >> 5;
    const int wm   = wid & 1;
    const int wn   = wid >> 1;
    const int bm   = blockIdx.y * 128;
    const int bn   = blockIdx.x * 128;
    const int nk   = K / BK;

    float acc[4][4][4];
#pragma unroll
    for (int i = 0; i < 4; i++)
#pragma unroll
        for (int j = 0; j < 4; j++)
#pragma unroll
            for (int e = 0; e < 4; e++) acc[i][j][e] = 0.f;

    const int r0 = tid >> 3;
    const int c0 = (tid & 7) * 8;
    uint32_t sbase = smem_u32(dsm);

    uint32_t aoff[4];
#pragma unroll
    for (int mi = 0; mi < 4; mi++) {
        int row = wm * 64 + mi * 16 + (lane & 15);
        aoff[mi] = (uint32_t)(row * ROWE + (lane >> 4) * 8) * 2;
    }
    uint32_t boffp[2];
#pragma unroll
    for (int pi = 0; pi < 2; pi++) {
        int l2  = lane & 15;
        int grp = lane >> 4;
        int row = wn * 32 + (pi * 2 + grp) * 8 + (l2 & 7);
        boffp[pi] = (uint32_t)(row * ROWE + ((l2 >> 3) & 1) * 8) * 2;
    }

#pragma unroll
    for (int j = 0; j < 2; j++) {
        uint32_t sa = sbase + j * STGB, sb = sa + OPB;
        int k0 = j * BK;
        int kA = (k0 < aW) ? k0 : k0 - aW;
        int kB = (k0 < bW) ? k0 : k0 - bW;
#pragma unroll
        for (int i = 0; i < 4; i++) {
            int r = r0 + i * 32;
            CP16(sa + (uint32_t)(r * ROWE + c0) * 2, A + (size_t)(bm + r) * K2 + kA + c0);
            CP16(sb + (uint32_t)(r * ROWE + c0) * 2, B + (size_t)(bn + r) * K2 + kB + c0);
        }
        CP_COMMIT();
    }

    int st = 0;
#pragma unroll 1
    for (int kt = 0; kt < nk; kt++) {
        asm volatile("cp.async.wait_group 1;" ::: "memory");
        __syncthreads();

        int jn = kt + 2;
        if (jn < nk) {
            int st2 = st + 2; if (st2 >= 3) st2 -= 3;
            uint32_t sa = sbase + (uint32_t)st2 * STGB, sb = sa + OPB;
            int k0 = jn * BK;
            int kA = (k0 < aW) ? k0 : k0 - aW;
            int kB = (k0 < bW) ? k0 : k0 - bW;
#pragma unroll
            for (int i = 0; i < 4; i++) {
                int r = r0 + i * 32;
                CP16(sa + (uint32_t)(r * ROWE + c0) * 2, A + (size_t)(bm + r) * K2 + kA + c0);
                CP16(sb + (uint32_t)(r * ROWE + c0) * 2, B + (size_t)(bn + r) * K2 + kB + c0);
            }
        }
        CP_COMMIT();

        uint32_t sa = sbase + (uint32_t)st * STGB, sb = sa + OPB;

#pragma unroll
        for (int ksp = 0; ksp < 2; ksp++) {
            uint32_t a[2][4][4];
            uint32_t bp[2][2][4];
#pragma unroll
            for (int k2 = 0; k2 < 2; k2++) {
                uint32_t kadd = (uint32_t)((ksp * 2 + k2) * 16) * 2;
#pragma unroll
                for (int mi = 0; mi < 4; mi++) ldm_x4(a[k2][mi], sa + aoff[mi] + kadd);
#pragma unroll
                for (int pi = 0; pi < 2; pi++) ldm_x4(bp[k2][pi], sb + boffp[pi] + kadd);
            }
#pragma unroll
            for (int k2 = 0; k2 < 2; k2++)
#pragma unroll
                for (int mi = 0; mi < 4; mi++)
#pragma unroll
                    for (int ni = 0; ni < 4; ni++)
                        mma_bf16(acc[mi][ni], a[k2][mi], &bp[k2][ni >> 1][(ni & 1) * 2]);
        }
        if (++st == 3) st = 0;
    }

#pragma unroll
    for (int mi = 0; mi < 4; mi++) {
        int row = bm + wm * 64 + mi * 16 + (lane >> 2);
#pragma unroll
        for (int ni = 0; ni < 4; ni++) {
            int col = bn + wn * 32 + ni * 8 + (lane & 3) * 2;
            if (col < Nout) {
                *(float2*)(C + (size_t)row * ldc + col)       = make_float2(acc[mi][ni][0], acc[mi][ni][1]);
                *(float2*)(C + (size_t)(row + 8) * ldc + col) = make_float2(acc[mi][ni][2], acc[mi][ni][3]);
            }
        }
    }
}

// ---------------- merged fp32 -> bf16 hi/lo splits, vectorized 4/thread -----------
#define NSPLIT_A4 (BSN*DMODEL/4)
#define NSPLIT_B4 (NPAD_IP*DMODEL/4)
#define NSPLIT_C4 (DMODEL*DMODEL/4)

__global__ void split_all_k(const float* __restrict__ x, const float* __restrict__ ipw,
                            const float* __restrict__ opw)
{
    int gi = blockIdx.x * blockDim.x + threadIdx.x;
    const float* src;
    __nv_bfloat16* dst;
    int rows, idx;
    if (gi < NSPLIT_A4) {
        src = x; dst = g_xs; rows = BSN; idx = gi;
    } else if (gi < NSPLIT_A4 + NSPLIT_B4) {
        src = ipw; dst = g_ws; rows = DINP; idx = gi - NSPLIT_A4;
    } else if (gi < NSPLIT_A4 + NSPLIT_B4 + NSPLIT_C4) {
        src = opw; dst = g_w2s; rows = DMODEL; idx = gi - NSPLIT_A4 - NSPLIT_B4;
    } else return;
    int r = idx / (DMODEL / 4);
    int k4 = (idx % (DMODEL / 4)) * 4;
    float4 v = (r < rows) ? *(const float4*)(src + (size_t)r * DMODEL + k4)
                          : make_float4(0.f, 0.f, 0.f, 0.f);
    __nv_bfloat16 h0 = __float2bfloat16(v.x), h1 = __float2bfloat16(v.y);
    __nv_bfloat16 h2 = __float2bfloat16(v.z), h3 = __float2bfloat16(v.w);
    __nv_bfloat16 l0 = __float2bfloat16(v.x - __bfloat162float(h0));
    __nv_bfloat16 l1 = __float2bfloat16(v.y - __bfloat162float(h1));
    __nv_bfloat16 l2 = __float2bfloat16(v.z - __bfloat162float(h2));
    __nv_bfloat16 l3 = __float2bfloat16(v.w - __bfloat162float(h3));
    __nv_bfloat162 hp0 = __halves2bfloat162(h0, h1), hp1 = __halves2bfloat162(h2, h3);
    __nv_bfloat162 lp0 = __halves2bfloat162(l0, l1), lp1 = __halves2bfloat162(l2, l3);
    uint2 hu, lu;
    hu.x = *(uint32_t*)&hp0; hu.y = *(uint32_t*)&hp1;
    lu.x = *(uint32_t*)&lp0; lu.y = *(uint32_t*)&lp1;
    size_t b = (size_t)r * K2 + k4;
    *(uint2*)(dst + b)          = hu;
    *(uint2*)(dst + b + DMODEL) = lu;
}

// --------------- fused conv + per-chunk tile kernel (3 smem arrays, occ 4) ---------
#define RP 68

__global__ __launch_bounds__(256, 4) void chunk_k(const float* __restrict__ cw,
                                                  const float* __restrict__ cb,
                                                  const float* __restrict__ w_base)
{
    extern __shared__ float sh[];
    float (*sCT)[RP] = (float(*)[RP])sh;
    float (*sBT)[RP] = (float(*)[RP])(sh + 64 * RP);
    float (*sX)[RP]  = (float(*)[RP])(sh + 2 * 64 * RP);
    float (*sGL)[RP] = sCT;
    __shared__ float scum[64];
    __shared__ float smn[64];
    __shared__ float sds[64];

    int bh = blockIdx.x >> 6;
    int c  = blockIdx.x & 63;
    int b  = bh >> 4;
    int h  = bh & 15;
    int tid = threadIdx.x;
    size_t base = ((size_t)bh * SEQL + (size_t)c * CHUNKL) * HD;
    size_t abase = (size_t)bh * SEQL + c * 64;

    if (tid < 192) {
        int n = tid & 63;
        int sect = tid >> 6;
        int ch = sect * 1024 + h * 64 + n;
        float w0 = cw[ch * 4 + 0], w1 = cw[ch * 4 + 1];
        float w2 = cw[ch * 4 + 2], w3 = cw[ch * 4 + 3];
        float bias = cb[ch];
        size_t rowbase = ((size_t)b * SEQL + (size_t)c * 64) * DINP + ch;

        float h0 = 0.f, h1 = 0.f, h2 = 0.f;
        if (c > 0) {
            h0 = g_xw[rowbase - 3 * (size_t)DINP];
            h1 = g_xw[rowbase - 2 * (size_t)DINP];
            h2 = g_xw[rowbase - 1 * (size_t)DINP];
        }
#pragma unroll 1
        for (int l0 = 0; l0 < 64; l0 += 8) {
            float xv[8];
#pragma unroll
            for (int k = 0; k < 8; k++)
                xv[k] = g_xw[rowbase + (size_t)(l0 + k) * DINP];
#pragma unroll
            for (int k = 0; k < 8; k++) {
                float o = fmaf(h0, w0, fmaf(h1, w1, fmaf(h2, w2, fmaf(xv[k], w3, bias))));
                int l = l0 + k;
                if (sect == 0) {
                    sCT[n][l] = o;
                    g_Cm[base + (size_t)l * 64 + n] = o;
                } else if (sect == 1) {
                    sBT[n][l] = o;
                } else {
                    sX[l][n] = o;
                }
                h0 = h1; h1 = h2; h2 = xv[k];
            }
        }
    } else if (tid < 224) {
        int lane = tid & 31;
        float wbh = w_base[h];
        float v0 = g_xw[(size_t)(b * SEQL + c * 64 + 2 * lane)     * DINP + CONVD + h] * wbh;
        float v1 = g_xw[(size_t)(b * SEQL + c * 64 + 2 * lane + 1) * DINP + CONVD + h] * wbh;
        float s = v0 + v1;
#pragma unroll
        for (int o = 1; o < 32; o <<= 1) {
            float t = __shfl_up_sync(0xffffffffu, s, o);
            if (lane >= o) s += t;
        }
        float c1 = s, cc0 = s - v1;
        scum[2 * lane] = cc0; scum[2 * lane + 1] = c1;
        g_cumA[abase + 2 * lane] = cc0;
        g_cumA[abase + 2 * lane + 1] = c1;
        float mm = fminf(cc0, c1);
#pragma unroll
        for (int o = 1; o < 32; o <<= 1) {
            float t = __shfl_up_sync(0xffffffffu, mm, o);
            if (lane >= o) mm = fminf(mm, t);
        }
        float prev = __shfl_up_sync(0xffffffffu, mm, 1);
        if (lane == 0) prev = 1e30f;
        smn[2 * lane]     = fminf(prev, cc0);
        smn[2 * lane + 1] = fminf(prev, fminf(cc0, c1));
        float mtot = __shfl_sync(0xffffffffu, mm, 31);
        float d0 = __expf(mtot - cc0), d1 = __expf(mtot - c1);
        sds[2 * lane] = d0; sds[2 * lane + 1] = d1;
        float nd = d0 + d1;
#pragma unroll
        for (int o = 16; o; o >>= 1) nd += __shfl_xor_sync(0xffffffffu, nd, o);
        float ctot = __shfl_sync(0xffffffffu, c1, 31);
        if (lane == 0) { g_Atot[bh * NCH + c] = ctot; g_ndec[bh * NCH + c] = nd; }
    }
    __syncthreads();

    int tj = (tid & 15) * 4;
    int ti = (tid >> 4) * 4;

    float gl4[4][4];
    float nsum[4] = {0.f, 0.f, 0.f, 0.f};
    {
        float r[4][4];
#pragma unroll
        for (int a = 0; a < 4; a++)
#pragma unroll
            for (int b2 = 0; b2 < 4; b2++) r[a][b2] = 0.f;
#pragma unroll 4
        for (int n = 0; n < 64; n++) {
            float4 cv = *(const float4*)&sCT[n][ti];
            float4 bv = *(const float4*)&sBT[n][tj];
            float cva[4] = {cv.x, cv.y, cv.z, cv.w};
            float bva[4] = {bv.x, bv.y, bv.z, bv.w};
#pragma unroll
            for (int a = 0; a < 4; a++)
#pragma unroll
                for (int b2 = 0; b2 < 4; b2++) r[a][b2] = fmaf(cva[a], bva[b2], r[a][b2]);
        }
#pragma unroll
        for (int a = 0; a < 4; a++) {
            int i = ti + a;
            float m = smn[i];
#pragma unroll
            for (int b2 = 0; b2 < 4; b2++) {
                float e = __expf(m - scum[tj + b2]);
                bool in = (tj + b2 <= i);
                gl4[a][b2] = in ? r[a][b2] * e : 0.f;
                nsum[a] += in ? e : 0.f;
            }
        }
    }
#pragma unroll
    for (int a = 0; a < 4; a++) {
#pragma unroll
        for (int o = 8; o; o >>= 1)
            nsum[a] += __shfl_xor_sync(0xffffffffu, nsum[a], o);
    }
    if ((tid & 15) == 0) {
#pragma unroll
        for (int a = 0; a < 4; a++)
            g_ndiag[abase + ti + a] = nsum[a];
    }
    __syncthreads();

#pragma unroll
    for (int a = 0; a < 4; a++)
        *(float4*)&sGL[ti + a][tj] = make_float4(gl4[a][0], gl4[a][1], gl4[a][2], gl4[a][3]);
    __syncthreads();

    {
        float r[4][4];
#pragma unroll
        for (int a = 0; a < 4; a++)
#pragma unroll
            for (int b2 = 0; b2 < 4; b2++) r[a][b2] = 0.f;
#pragma unroll 4
        for (int j = 0; j < 64; j++) {
            float4 xv = *(const float4*)&sX[j][tj];
            float xva[4] = {xv.x, xv.y, xv.z, xv.w};
            float gl[4];
#pragma unroll
            for (int a = 0; a < 4; a++) gl[a] = sGL[ti + a][j];
#pragma unroll
            for (int a = 0; a < 4; a++)
#pragma unroll
                for (int b2 = 0; b2 < 4; b2++) r[a][b2] = fmaf(gl[a], xva[b2], r[a][b2]);
        }
#pragma unroll
        for (int a = 0; a < 4; a++)
            *(float4*)(g_Ydiag + base + (size_t)(ti + a) * 64 + tj)
                = make_float4(r[a][0], r[a][1], r[a][2], r[a][3]);
    }
    {
        float r[4][4];
#pragma unroll
        for (int a = 0; a < 4; a++)
#pragma unroll
            for (int b2 = 0; b2 < 4; b2++) r[a][b2] = 0.f;
#pragma unroll 4
        for (int l = 0; l < 64; l++) {
            float d = sds[l];
            float4 xv = *(const float4*)&sX[l][tj];
            float xva[4] = {xv.x * d, xv.y * d, xv.z * d, xv.w * d};
            float bva[4];
#pragma unroll
            for (int a = 0; a < 4; a++) bva[a] = sBT[ti + a][l];
#pragma unroll
            for (int a = 0; a < 4; a++)
#pragma unroll
                for (int b2 = 0; b2 < 4; b2++) r[a][b2] = fmaf(bva[a], xva[b2], r[a][b2]);
        }
        size_t sb = ((size_t)bh * NCH + c) * 4096;
#pragma unroll
        for (int a = 0; a < 4; a++)
            *(float4*)(g_states + sb + (size_t)(ti + a) * 64 + tj)
                = make_float4(r[a][0], r[a][1], r[a][2], r[a][3]);
    }
}

// --------------- chunk recurrence scan: coefficient-hoisted, 512 blocks ------------
__global__ __launch_bounds__(256) void scan_k()
{
    __shared__ float sf[64];
    __shared__ float sg[64];
    __shared__ float snd[64];

    int bh   = blockIdx.x >> 4;
    int part = blockIdx.x & 15;
    int tid  = threadIdx.x;
    int e0   = part * 256 + tid;
    size_t sb = (size_t)bh * NCH * 4096;

    if (tid < 32) {
        int lane = tid;
        float a0 = (2 * lane < 63)     ? g_Atot[bh * NCH + 2 * lane]     : 0.f;
        float a1 = (2 * lane + 1 < 63) ? g_Atot[bh * NCH + 2 * lane + 1] : 0.f;
        float s = a0 + a1;
#pragma unroll
        for (int o = 1; o < 32; o <<= 1) {
            float t = __shfl_up_sync(0xffffffffu, s, o);
            if (lane >= o) s += t;
        }
        float cc1 = s, cc0 = s - a1;
        float mm = fminf(cc0, cc1);
#pragma unroll
        for (int o = 1; o < 32; o <<= 1) {
            float t = __shfl_up_sync(0xffffffffu, mm, o);
            if (lane >= o) mm = fminf(mm, t);
        }
        float prevmm = __shfl_up_sync(0xffffffffu, mm, 1);
        if (lane == 0) prevmm = 0.f;
        prevmm = fminf(prevmm, 0.f);
        float m0 = fminf(prevmm, cc0);
        float m1 = fminf(m0, cc1);
        sf[2 * lane]     = __expf(m0 - prevmm);
        sf[2 * lane + 1] = __expf(m1 - m0);
        sg[2 * lane]     = __expf(m0 - cc0);
        sg[2 * lane + 1] = __expf(m1 - cc1);
        snd[2 * lane]     = (2 * lane < 63)     ? g_ndec[bh * NCH + 2 * lane]     : 0.f;
        snd[2 * lane + 1] = (2 * lane + 1 < 63) ? g_ndec[bh * NCH + 2 * lane + 1] : 0.f;
    }
    __syncthreads();

    if (part == 0 && tid == 32) {
        float nacc = 0.f;
        g_nnew[bh * NCH] = 0.f;
#pragma unroll 1
        for (int z = 0; z < 63; z++) {
            nacc = nacc * sf[z] + sg[z] * snd[z];
            g_nnew[bh * NCH + z + 1] = nacc;
        }
    }

    float pf[4];
#pragma unroll
    for (int z = 0; z < 4; z++) pf[z] = g_states[sb + (size_t)z * 4096 + e0];

    float r = 0.f;
    g_nstates[sb + e0] = 0.f;
#pragma unroll 1
    for (int z = 0; z < 63; z++) {
        float s = pf[z & 3];
        if (z + 4 < 63) pf[z & 3] = g_states[sb + (size_t)(z + 4) * 4096 + e0];
        r = r * sf[z] + sg[z] * s;
        g_nstates[sb + (size_t)(z + 1) * 4096 + e0] = r;
    }
}

// --------------- Y_off + combine + normalize + bf16 split (hi,lo layout) ----------
__global__ __launch_bounds__(256) void yoff_k()
{
    __shared__ float sCT[64][RP];
    __shared__ float sST[64][RP];
    __shared__ float scum[64];
    __shared__ float sdo[64];

    int bh = blockIdx.x >> 6;
    int c  = blockIdx.x & 63;
    int b  = bh >> 4;
    int h  = bh & 15;
    int tid = threadIdx.x;
    size_t baseC = ((size_t)bh * SEQL + (size_t)c * 64) * HD;
    size_t baseS = ((size_t)bh * NCH + c) * 4096;

    {
        const float4* pC = (const float4*)(g_Cm + baseC);
        const float4* pS = (const float4*)(g_nstates + baseS);
        for (int i4 = tid; i4 < 1024; i4 += 256) {
            int l = i4 >> 4, n4 = (i4 & 15) * 4;
            float4 v = pC[i4];
            sCT[n4][l] = v.x; sCT[n4+1][l] = v.y; sCT[n4+2][l] = v.z; sCT[n4+3][l] = v.w;
            v = pS[i4];
            *(float4*)&sST[l][n4] = v;
        }
    }
    if (tid < 32) {
        float a0 = g_cumA[(size_t)bh * SEQL + c * 64 + 2 * tid];
        float a1 = g_cumA[(size_t)bh * SEQL + c * 64 + 2 * tid + 1];
        scum[2 * tid] = a0; scum[2 * tid + 1] = a1;
        float mx = fmaxf(a0, a1);
#pragma unroll
        for (int o = 16; o; o >>= 1) mx = fmaxf(mx, __shfl_xor_sync(0xffffffffu, mx, o));
        sdo[2 * tid]     = __expf(a0 - mx);
        sdo[2 * tid + 1] = __expf(a1 - mx);
    }
    __syncthreads();

    float nn = g_nnew[bh * NCH + c];
    int tl = (tid >> 4) * 4;
    int tp = (tid & 15) * 4;
    float r[4][4];
#pragma unroll
    for (int a = 0; a < 4; a++)
#pragma unroll
        for (int b2 = 0; b2 < 4; b2++) r[a][b2] = 0.f;
#pragma unroll 4
    for (int n = 0; n < 64; n++) {
        float4 cv = *(const float4*)&sCT[n][tl];
        float4 sv = *(const float4*)&sST[n][tp];
        float cva[4] = {cv.x, cv.y, cv.z, cv.w};
        float sva[4] = {sv.x, sv.y, sv.z, sv.w};
#pragma unroll
        for (int a = 0; a < 4; a++)
#pragma unroll
            for (int b2 = 0; b2 < 4; b2++) r[a][b2] = fmaf(cva[a], sva[b2], r[a][b2]);
    }
#pragma unroll
    for (int a = 0; a < 4; a++) {
        int l = tl + a;
        float d = sdo[l];
        float nm = g_ndiag[(size_t)bh * SEQL + c * 64 + l] + nn * d;
        float inv = 1.f / nm;
        int s = c * 64 + l;
        size_t rowb = ((size_t)b * SEQL + s) * K2 + h * 64;
        const float4 yv = *(const float4*)(g_Ydiag + baseC + (size_t)l * 64 + tp);
        float v0 = (yv.x + d * r[a][0]) * inv;
        float v1 = (yv.y + d * r[a][1]) * inv;
        float v2 = (yv.z + d * r[a][2]) * inv;
        float v3 = (yv.w + d * r[a][3]) * inv;
        __nv_bfloat16 h0 = __float2bfloat16(v0), h1 = __float2bfloat16(v1);
        __nv_bfloat16 h2 = __float2bfloat16(v2), h3 = __float2bfloat16(v3);
        __nv_bfloat16 l0 = __float2bfloat16(v0 - __bfloat162float(h0));
        __nv_bfloat16 l1 = __float2bfloat16(v1 - __bfloat162float(h1));
        __nv_bfloat16 l2 = __float2bfloat16(v2 - __bfloat162float(h2));
        __nv_bfloat16 l3 = __float2bfloat16(v3 - __bfloat162float(h3));
        __nv_bfloat162 hp0 = __halves2bfloat162(h0, h1), hp1 = __halves2bfloat162(h2, h3);
        __nv_bfloat162 lp0 = __halves2bfloat162(l0, l1), lp1 = __halves2bfloat162(l2, l3);
        uint2 hu, lu;
        hu.x = *(uint32_t*)&hp0; hu.y = *(uint32_t*)&hp1;
        lu.x = *(uint32_t*)&lp0; lu.y = *(uint32_t*)&lp1;
        *(uint2*)(g_ys + rowb + tp)          = hu;
        *(uint2*)(g_ys + rowb + tp + DMODEL) = lu;
    }
}

// ------------------------------- launch ---------------------------------------------
extern "C" void kernel_launch(void* const* d_in, const int* in_sizes, int n_in,
                              void* d_out, int out_size)
{
    const float* x   = (const float*)d_in[0];
    const float* ipw = (const float*)d_in[1];
    const float* cw  = (const float*)d_in[2];
    const float* cb  = (const float*)d_in[3];
    const float* wb  = (const float*)d_in[4];
    const float* opw = (const float*)d_in[5];
    float* out = (float*)d_out;

    float *p_xw = nullptr;
    __nv_bfloat16 *p_xs, *p_ws, *p_w2s, *p_ys;
    cudaGetSymbolAddress((void**)&p_xw, g_xw);
    cudaGetSymbolAddress((void**)&p_xs, g_xs);
    cudaGetSymbolAddress((void**)&p_ws, g_ws);
    cudaGetSymbolAddress((void**)&p_w2s, g_w2s);
    cudaGetSymbolAddress((void**)&p_ys, g_ys);

    const int SMEM_CHUNK = 3 * 64 * RP * 4;
    cudaFuncSetAttribute(chunk_k, cudaFuncAttributeMaxDynamicSharedMemorySize, SMEM_CHUNK);
    const int SMEM_GEMM = NSTG * (int)STGB;
    cudaFuncSetAttribute(mma_gemm_k, cudaFuncAttributeMaxDynamicSharedMemorySize, SMEM_GEMM);

    // 0) merged bf16 splits (vectorized)
    {
        int total = NSPLIT_A4 + NSPLIT_B4 + NSPLIT_C4;
        split_all_k<<<(total + 255) / 256, 256>>>(x, ipw, opw);
    }

    // 1) in_proj via HMMA (grid-tiled — persistent variants regressed twice)
    {
        dim3 g(NPAD_IP / 128, BSN / 128);
        mma_gemm_k<<<g, 256, SMEM_GEMM>>>(p_xs, p_ws, p_xw, K3, DINP, DINP, 1024, 2048);
    }

    // 2) fused conv + per-chunk tiles
    chunk_k<<<BHN * NCH, 256, SMEM_CHUNK>>>(cw, cb, wb);

    // 3) chunk recurrence scan
    scan_k<<<BHN * 16, 256>>>();

    // 4) off-diagonal + normalize + fused bf16 split
    yoff_k<<<BHN * NCH, 256>>>();

    // 5) out_proj via HMMA
    {
        dim3 g(DMODEL / 128, BSN / 128);
        mma_gemm_k<<<g, 256, SMEM_GEMM>>>(p_ys, p_w2s, out, K3, DMODEL, DMODEL, 1024, 2048);
    }
}

// round 17
// speedup vs baseline: 1.1113x; 1.0002x over previous
#include <cuda_runtime.h>
#include <cuda_bf16.h>
#include <math.h>
#include <stdint.h>

#define BATCHN 2
#define SEQL   4096
#define DMODEL 1024
#define NH     16
#define HD     64
#define CHUNKL 64
#define NCH    64
#define CONVD  3072
#define DINP   3088
#define BHN    (BATCHN*NH)
#define BSN    (BATCHN*SEQL)
#define K3     3072
#define K2     2048
#define NPAD_IP 3200

// ---------------- scratch ------------------------------------------------------
__device__ float g_xw[(size_t)BSN*DINP];
__device__ float g_Cm[(size_t)BHN*SEQL*HD];
__device__ float g_cumA[(size_t)BHN*SEQL];
__device__ float g_states[(size_t)BHN*NCH*HD*HD];
__device__ float g_nstates[(size_t)BHN*NCH*HD*HD];
__device__ float g_Atot[BHN*NCH];
__device__ float g_ndec[BHN*NCH];
__device__ float g_nnew[BHN*NCH];
__device__ float g_Ydiag[(size_t)BHN*SEQL*HD];
__device__ float g_ndiag[(size_t)BHN*SEQL];
__device__ __nv_bfloat16 g_xs[(size_t)BSN*K2];
__device__ __nv_bfloat16 g_ws[(size_t)NPAD_IP*K2];
__device__ __nv_bfloat16 g_w2s[(size_t)DMODEL*K2];
__device__ __nv_bfloat16 g_ys[(size_t)BSN*K2];

// ---------------- helpers ------------------------------------------------------
__device__ __forceinline__ uint32_t smem_u32(const void* p) {
    uint32_t a;
    asm("{ .reg .u64 t; cvta.to.shared.u64 t, %1; cvt.u32.u64 %0, t; }" : "=r"(a) : "l"(p));
    return a;
}
#define CP16(dst, src)  asm volatile("cp.async.cg.shared.global [%0], [%1], 16;" :: "r"(dst), "l"(src) : "memory")
#define CP_COMMIT()     asm volatile("cp.async.commit_group;" ::: "memory")

__device__ __forceinline__ void ldm_x4(uint32_t* r, uint32_t addr) {
    asm volatile("ldmatrix.sync.aligned.m8n8.x4.shared.b16 {%0,%1,%2,%3}, [%4];"
        : "=r"(r[0]), "=r"(r[1]), "=r"(r[2]), "=r"(r[3]) : "r"(addr));
}
__device__ __forceinline__ void mma_bf16(float* c, const uint32_t* a, const uint32_t* b) {
    asm volatile("mma.sync.aligned.m16n8k16.row.col.f32.bf16.bf16.f32 "
        "{%0,%1,%2,%3},{%4,%5,%6,%7},{%8,%9},{%0,%1,%2,%3};"
        : "+f"(c[0]), "+f"(c[1]), "+f"(c[2]), "+f"(c[3])
        : "r"(a[0]), "r"(a[1]), "r"(a[2]), "r"(a[3]), "r"(b[0]), "r"(b[1]));
}

// ---------------- bf16 HMMA GEMM (BK=64, 3 stages, k-aliased operands) -----------
#define BK    64
#define ROWE  72
#define NSTG  3
#define STGB  (2u * 128 * ROWE * 2)
#define OPB   (128u * ROWE * 2)

__global__ __launch_bounds__(256, 2) void mma_gemm_k(
    const __nv_bfloat16* __restrict__ A, const __nv_bfloat16* __restrict__ B,
    float* __restrict__ C, int K, int Nout, int ldc, int aW, int bW)
{
    extern __shared__ __align__(16) __nv_bfloat16 dsm[];

    const int tid  = threadIdx.x;
    const int lane = tid & 31;
    const int wid  = tid >> 5;
    const int wm   = wid & 1;
    const int wn   = wid >> 1;
    const int bm   = blockIdx.y * 128;
    const int bn   = blockIdx.x * 128;
    const int nk   = K / BK;

    float acc[4][4][4];
#pragma unroll
    for (int i = 0; i < 4; i++)
#pragma unroll
        for (int j = 0; j < 4; j++)
#pragma unroll
            for (int e = 0; e < 4; e++) acc[i][j][e] = 0.f;

    const int r0 = tid >> 3;
    const int c0 = (tid & 7) * 8;
    uint32_t sbase = smem_u32(dsm);

    uint32_t aoff[4];
#pragma unroll
    for (int mi = 0; mi < 4; mi++) {
        int row = wm * 64 + mi * 16 + (lane & 15);
        aoff[mi] = (uint32_t)(row * ROWE + (lane >> 4) * 8) * 2;
    }
    uint32_t boffp[2];
#pragma unroll
    for (int pi = 0; pi < 2; pi++) {
        int l2  = lane & 15;
        int grp = lane >> 4;
        int row = wn * 32 + (pi * 2 + grp) * 8 + (l2 & 7);
        boffp[pi] = (uint32_t)(row * ROWE + ((l2 >> 3) & 1) * 8) * 2;
    }

#pragma unroll
    for (int j = 0; j < 2; j++) {
        uint32_t sa = sbase + j * STGB, sb = sa + OPB;
        int k0 = j * BK;
        int kA = (k0 < aW) ? k0 : k0 - aW;
        int kB = (k0 < bW) ? k0 : k0 - bW;
#pragma unroll
        for (int i = 0; i < 4; i++) {
            int r = r0 + i * 32;
            CP16(sa + (uint32_t)(r * ROWE + c0) * 2, A + (size_t)(bm + r) * K2 + kA + c0);
            CP16(sb + (uint32_t)(r * ROWE + c0) * 2, B + (size_t)(bn + r) * K2 + kB + c0);
        }
        CP_COMMIT();
    }

    int st = 0;
#pragma unroll 1
    for (int kt = 0; kt < nk; kt++) {
        asm volatile("cp.async.wait_group 1;" ::: "memory");
        __syncthreads();

        int jn = kt + 2;
        if (jn < nk) {
            int st2 = st + 2; if (st2 >= 3) st2 -= 3;
            uint32_t sa = sbase + (uint32_t)st2 * STGB, sb = sa + OPB;
            int k0 = jn * BK;
            int kA = (k0 < aW) ? k0 : k0 - aW;
            int kB = (k0 < bW) ? k0 : k0 - bW;
#pragma unroll
            for (int i = 0; i < 4; i++) {
                int r = r0 + i * 32;
                CP16(sa + (uint32_t)(r * ROWE + c0) * 2, A + (size_t)(bm + r) * K2 + kA + c0);
                CP16(sb + (uint32_t)(r * ROWE + c0) * 2, B + (size_t)(bn + r) * K2 + kB + c0);
            }
        }
        CP_COMMIT();

        uint32_t sa = sbase + (uint32_t)st * STGB, sb = sa + OPB;

#pragma unroll
        for (int ksp = 0; ksp < 2; ksp++) {
            uint32_t a[2][4][4];
            uint32_t bp[2][2][4];
#pragma unroll
            for (int k2 = 0; k2 < 2; k2++) {
                uint32_t kadd = (uint32_t)((ksp * 2 + k2) * 16) * 2;
#pragma unroll
                for (int mi = 0; mi < 4; mi++) ldm_x4(a[k2][mi], sa + aoff[mi] + kadd);
#pragma unroll
                for (int pi = 0; pi < 2; pi++) ldm_x4(bp[k2][pi], sb + boffp[pi] + kadd);
            }
#pragma unroll
            for (int k2 = 0; k2 < 2; k2++)
#pragma unroll
                for (int mi = 0; mi < 4; mi++)
#pragma unroll
                    for (int ni = 0; ni < 4; ni++)
                        mma_bf16(acc[mi][ni], a[k2][mi], &bp[k2][ni >> 1][(ni & 1) * 2]);
        }
        if (++st == 3) st = 0;
    }

#pragma unroll
    for (int mi = 0; mi < 4; mi++) {
        int row = bm + wm * 64 + mi * 16 + (lane >> 2);
#pragma unroll
        for (int ni = 0; ni < 4; ni++) {
            int col = bn + wn * 32 + ni * 8 + (lane & 3) * 2;
            if (col < Nout) {
                *(float2*)(C + (size_t)row * ldc + col)       = make_float2(acc[mi][ni][0], acc[mi][ni][1]);
                *(float2*)(C + (size_t)(row + 8) * ldc + col) = make_float2(acc[mi][ni][2], acc[mi][ni][3]);
            }
        }
    }
}

// ---------------- merged fp32 -> bf16 hi/lo splits, vectorized 4/thread -----------
#define NSPLIT_A4 (BSN*DMODEL/4)
#define NSPLIT_B4 (NPAD_IP*DMODEL/4)
#define NSPLIT_C4 (DMODEL*DMODEL/4)

__global__ void split_all_k(const float* __restrict__ x, const float* __restrict__ ipw,
                            const float* __restrict__ opw)
{
    int gi = blockIdx.x * blockDim.x + threadIdx.x;
    const float* src;
    __nv_bfloat16* dst;
    int rows, idx;
    if (gi < NSPLIT_A4) {
        src = x; dst = g_xs; rows = BSN; idx = gi;
    } else if (gi < NSPLIT_A4 + NSPLIT_B4) {
        src = ipw; dst = g_ws; rows = DINP; idx = gi - NSPLIT_A4;
    } else if (gi < NSPLIT_A4 + NSPLIT_B4 + NSPLIT_C4) {
        src = opw; dst = g_w2s; rows = DMODEL; idx = gi - NSPLIT_A4 - NSPLIT_B4;
    } else return;
    int r = idx / (DMODEL / 4);
    int k4 = (idx % (DMODEL / 4)) * 4;
    float4 v = (r < rows) ? *(const float4*)(src + (size_t)r * DMODEL + k4)
                          : make_float4(0.f, 0.f, 0.f, 0.f);
    __nv_bfloat16 h0 = __float2bfloat16(v.x), h1 = __float2bfloat16(v.y);
    __nv_bfloat16 h2 = __float2bfloat16(v.z), h3 = __float2bfloat16(v.w);
    __nv_bfloat16 l0 = __float2bfloat16(v.x - __bfloat162float(h0));
    __nv_bfloat16 l1 = __float2bfloat16(v.y - __bfloat162float(h1));
    __nv_bfloat16 l2 = __float2bfloat16(v.z - __bfloat162float(h2));
    __nv_bfloat16 l3 = __float2bfloat16(v.w - __bfloat162float(h3));
    __nv_bfloat162 hp0 = __halves2bfloat162(h0, h1), hp1 = __halves2bfloat162(h2, h3);
    __nv_bfloat162 lp0 = __halves2bfloat162(l0, l1), lp1 = __halves2bfloat162(l2, l3);
    uint2 hu, lu;
    hu.x = *(uint32_t*)&hp0; hu.y = *(uint32_t*)&hp1;
    lu.x = *(uint32_t*)&lp0; lu.y = *(uint32_t*)&lp1;
    size_t b = (size_t)r * K2 + k4;
    *(uint2*)(dst + b)          = hu;
    *(uint2*)(dst + b + DMODEL) = lu;
}

// --------------- fused conv + per-chunk tile kernel (3 smem arrays, occ 4) ---------
#define RP 68

__global__ __launch_bounds__(256, 4) void chunk_k(const float* __restrict__ cw,
                                                  const float* __restrict__ cb,
                                                  const float* __restrict__ w_base)
{
    extern __shared__ float sh[];
    float (*sCT)[RP] = (float(*)[RP])sh;
    float (*sBT)[RP] = (float(*)[RP])(sh + 64 * RP);
    float (*sX)[RP]  = (float(*)[RP])(sh + 2 * 64 * RP);
    float (*sGL)[RP] = sCT;
    __shared__ float scum[64];
    __shared__ float smn[64];
    __shared__ float sds[64];

    int bh = blockIdx.x >> 6;
    int c  = blockIdx.x & 63;
    int b  = bh >> 4;
    int h  = bh & 15;
    int tid = threadIdx.x;
    size_t base = ((size_t)bh * SEQL + (size_t)c * CHUNKL) * HD;
    size_t abase = (size_t)bh * SEQL + c * 64;

    if (tid < 192) {
        int n = tid & 63;
        int sect = tid >> 6;
        int ch = sect * 1024 + h * 64 + n;
        float w0 = cw[ch * 4 + 0], w1 = cw[ch * 4 + 1];
        float w2 = cw[ch * 4 + 2], w3 = cw[ch * 4 + 3];
        float bias = cb[ch];
        size_t rowbase = ((size_t)b * SEQL + (size_t)c * 64) * DINP + ch;

        float h0 = 0.f, h1 = 0.f, h2 = 0.f;
        if (c > 0) {
            h0 = g_xw[rowbase - 3 * (size_t)DINP];
            h1 = g_xw[rowbase - 2 * (size_t)DINP];
            h2 = g_xw[rowbase - 1 * (size_t)DINP];
        }
#pragma unroll 1
        for (int l0 = 0; l0 < 64; l0 += 8) {
            float xv[8];
#pragma unroll
            for (int k = 0; k < 8; k++)
                xv[k] = g_xw[rowbase + (size_t)(l0 + k) * DINP];
#pragma unroll
            for (int k = 0; k < 8; k++) {
                float o = fmaf(h0, w0, fmaf(h1, w1, fmaf(h2, w2, fmaf(xv[k], w3, bias))));
                int l = l0 + k;
                if (sect == 0) {
                    sCT[n][l] = o;
                    g_Cm[base + (size_t)l * 64 + n] = o;
                } else if (sect == 1) {
                    sBT[n][l] = o;
                } else {
                    sX[l][n] = o;
                }
                h0 = h1; h1 = h2; h2 = xv[k];
            }
        }
    } else if (tid < 224) {
        int lane = tid & 31;
        float wbh = w_base[h];
        float v0 = g_xw[(size_t)(b * SEQL + c * 64 + 2 * lane)     * DINP + CONVD + h] * wbh;
        float v1 = g_xw[(size_t)(b * SEQL + c * 64 + 2 * lane + 1) * DINP + CONVD + h] * wbh;
        float s = v0 + v1;
#pragma unroll
        for (int o = 1; o < 32; o <<= 1) {
            float t = __shfl_up_sync(0xffffffffu, s, o);
            if (lane >= o) s += t;
        }
        float c1 = s, cc0 = s - v1;
        scum[2 * lane] = cc0; scum[2 * lane + 1] = c1;
        g_cumA[abase + 2 * lane] = cc0;
        g_cumA[abase + 2 * lane + 1] = c1;
        float mm = fminf(cc0, c1);
#pragma unroll
        for (int o = 1; o < 32; o <<= 1) {
            float t = __shfl_up_sync(0xffffffffu, mm, o);
            if (lane >= o) mm = fminf(mm, t);
        }
        float prev = __shfl_up_sync(0xffffffffu, mm, 1);
        if (lane == 0) prev = 1e30f;
        smn[2 * lane]     = fminf(prev, cc0);
        smn[2 * lane + 1] = fminf(prev, fminf(cc0, c1));
        float mtot = __shfl_sync(0xffffffffu, mm, 31);
        float d0 = __expf(mtot - cc0), d1 = __expf(mtot - c1);
        sds[2 * lane] = d0; sds[2 * lane + 1] = d1;
        float nd = d0 + d1;
#pragma unroll
        for (int o = 16; o; o >>= 1) nd += __shfl_xor_sync(0xffffffffu, nd, o);
        float ctot = __shfl_sync(0xffffffffu, c1, 31);
        if (lane == 0) { g_Atot[bh * NCH + c] = ctot; g_ndec[bh * NCH + c] = nd; }
    }
    __syncthreads();

    int tj = (tid & 15) * 4;
    int ti = (tid >> 4) * 4;

    float gl4[4][4];
    float nsum[4] = {0.f, 0.f, 0.f, 0.f};
    {
        float r[4][4];
#pragma unroll
        for (int a = 0; a < 4; a++)
#pragma unroll
            for (int b2 = 0; b2 < 4; b2++) r[a][b2] = 0.f;
#pragma unroll 4
        for (int n = 0; n < 64; n++) {
            float4 cv = *(const float4*)&sCT[n][ti];
            float4 bv = *(const float4*)&sBT[n][tj];
            float cva[4] = {cv.x, cv.y, cv.z, cv.w};
            float bva[4] = {bv.x, bv.y, bv.z, bv.w};
#pragma unroll
            for (int a = 0; a < 4; a++)
#pragma unroll
                for (int b2 = 0; b2 < 4; b2++) r[a][b2] = fmaf(cva[a], bva[b2], r[a][b2]);
        }
#pragma unroll
        for (int a = 0; a < 4; a++) {
            int i = ti + a;
            float m = smn[i];
#pragma unroll
            for (int b2 = 0; b2 < 4; b2++) {
                float e = __expf(m - scum[tj + b2]);
                bool in = (tj + b2 <= i);
                gl4[a][b2] = in ? r[a][b2] * e : 0.f;
                nsum[a] += in ? e : 0.f;
            }
        }
    }
#pragma unroll
    for (int a = 0; a < 4; a++) {
#pragma unroll
        for (int o = 8; o; o >>= 1)
            nsum[a] += __shfl_xor_sync(0xffffffffu, nsum[a], o);
    }
    if ((tid & 15) == 0) {
#pragma unroll
        for (int a = 0; a < 4; a++)
            g_ndiag[abase + ti + a] = nsum[a];
    }
    __syncthreads();

#pragma unroll
    for (int a = 0; a < 4; a++)
        *(float4*)&sGL[ti + a][tj] = make_float4(gl4[a][0], gl4[a][1], gl4[a][2], gl4[a][3]);
    __syncthreads();

    // GEMM2: Y[i][p] = sum_j GL[i][j] X[j][p]  (both operands float4)
    {
        float r[4][4];
#pragma unroll
        for (int a = 0; a < 4; a++)
#pragma unroll
            for (int b2 = 0; b2 < 4; b2++) r[a][b2] = 0.f;
#pragma unroll 2
        for (int j0 = 0; j0 < 64; j0 += 4) {
            float4 glv[4], xv4[4];
#pragma unroll
            for (int a = 0; a < 4; a++) glv[a] = *(const float4*)&sGL[ti + a][j0];
#pragma unroll
            for (int q = 0; q < 4; q++) xv4[q] = *(const float4*)&sX[j0 + q][tj];
#pragma unroll
            for (int a = 0; a < 4; a++) {
                float ga[4] = {glv[a].x, glv[a].y, glv[a].z, glv[a].w};
#pragma unroll
                for (int q = 0; q < 4; q++) {
                    r[a][0] = fmaf(ga[q], xv4[q].x, r[a][0]);
                    r[a][1] = fmaf(ga[q], xv4[q].y, r[a][1]);
                    r[a][2] = fmaf(ga[q], xv4[q].z, r[a][2]);
                    r[a][3] = fmaf(ga[q], xv4[q].w, r[a][3]);
                }
            }
        }
#pragma unroll
        for (int a = 0; a < 4; a++)
            *(float4*)(g_Ydiag + base + (size_t)(ti + a) * 64 + tj)
                = make_float4(r[a][0], r[a][1], r[a][2], r[a][3]);
    }
    // GEMM3: statesT[n][p] = sum_l B[l][n] * ds_l * X[l][p]  (both operands float4)
    {
        float r[4][4];
#pragma unroll
        for (int a = 0; a < 4; a++)
#pragma unroll
            for (int b2 = 0; b2 < 4; b2++) r[a][b2] = 0.f;
#pragma unroll 2
        for (int l0 = 0; l0 < 64; l0 += 4) {
            float4 bv4[4], xv4[4];
#pragma unroll
            for (int a = 0; a < 4; a++) bv4[a] = *(const float4*)&sBT[ti + a][l0];
#pragma unroll
            for (int q = 0; q < 4; q++) {
                float d = sds[l0 + q];
                float4 xv = *(const float4*)&sX[l0 + q][tj];
                xv4[q] = make_float4(xv.x * d, xv.y * d, xv.z * d, xv.w * d);
            }
#pragma unroll
            for (int a = 0; a < 4; a++) {
                float ba[4] = {bv4[a].x, bv4[a].y, bv4[a].z, bv4[a].w};
#pragma unroll
                for (int q = 0; q < 4; q++) {
                    r[a][0] = fmaf(ba[q], xv4[q].x, r[a][0]);
                    r[a][1] = fmaf(ba[q], xv4[q].y, r[a][1]);
                    r[a][2] = fmaf(ba[q], xv4[q].z, r[a][2]);
                    r[a][3] = fmaf(ba[q], xv4[q].w, r[a][3]);
                }
            }
        }
        size_t sb = ((size_t)bh * NCH + c) * 4096;
#pragma unroll
        for (int a = 0; a < 4; a++)
            *(float4*)(g_states + sb + (size_t)(ti + a) * 64 + tj)
                = make_float4(r[a][0], r[a][1], r[a][2], r[a][3]);
    }
}

// --------------- chunk recurrence scan: coefficient-hoisted, 512 blocks ------------
__global__ __launch_bounds__(256) void scan_k()
{
    __shared__ float sf[64];
    __shared__ float sg[64];
    __shared__ float snd[64];

    int bh   = blockIdx.x >> 4;
    int part = blockIdx.x & 15;
    int tid  = threadIdx.x;
    int e0   = part * 256 + tid;
    size_t sb = (size_t)bh * NCH * 4096;

    if (tid < 32) {
        int lane = tid;
        float a0 = (2 * lane < 63)     ? g_Atot[bh * NCH + 2 * lane]     : 0.f;
        float a1 = (2 * lane + 1 < 63) ? g_Atot[bh * NCH + 2 * lane + 1] : 0.f;
        float s = a0 + a1;
#pragma unroll
        for (int o = 1; o < 32; o <<= 1) {
            float t = __shfl_up_sync(0xffffffffu, s, o);
            if (lane >= o) s += t;
        }
        float cc1 = s, cc0 = s - a1;
        float mm = fminf(cc0, cc1);
#pragma unroll
        for (int o = 1; o < 32; o <<= 1) {
            float t = __shfl_up_sync(0xffffffffu, mm, o);
            if (lane >= o) mm = fminf(mm, t);
        }
        float prevmm = __shfl_up_sync(0xffffffffu, mm, 1);
        if (lane == 0) prevmm = 0.f;
        prevmm = fminf(prevmm, 0.f);
        float m0 = fminf(prevmm, cc0);
        float m1 = fminf(m0, cc1);
        sf[2 * lane]     = __expf(m0 - prevmm);
        sf[2 * lane + 1] = __expf(m1 - m0);
        sg[2 * lane]     = __expf(m0 - cc0);
        sg[2 * lane + 1] = __expf(m1 - cc1);
        snd[2 * lane]     = (2 * lane < 63)     ? g_ndec[bh * NCH + 2 * lane]     : 0.f;
        snd[2 * lane + 1] = (2 * lane + 1 < 63) ? g_ndec[bh * NCH + 2 * lane + 1] : 0.f;
    }
    __syncthreads();

    if (part == 0 && tid == 32) {
        float nacc = 0.f;
        g_nnew[bh * NCH] = 0.f;
#pragma unroll 1
        for (int z = 0; z < 63; z++) {
            nacc = nacc * sf[z] + sg[z] * snd[z];
            g_nnew[bh * NCH + z + 1] = nacc;
        }
    }

    float pf[4];
#pragma unroll
    for (int z = 0; z < 4; z++) pf[z] = g_states[sb + (size_t)z * 4096 + e0];

    float r = 0.f;
    g_nstates[sb + e0] = 0.f;
#pragma unroll 1
    for (int z = 0; z < 63; z++) {
        float s = pf[z & 3];
        if (z + 4 < 63) pf[z & 3] = g_states[sb + (size_t)(z + 4) * 4096 + e0];
        r = r * sf[z] + sg[z] * s;
        g_nstates[sb + (size_t)(z + 1) * 4096 + e0] = r;
    }
}

// --------------- Y_off + combine + normalize + bf16 split (hi,lo layout) ----------
__global__ __launch_bounds__(256, 4) void yoff_k()
{
    __shared__ float sCT[64][RP];
    __shared__ float sST[64][RP];
    __shared__ float scum[64];
    __shared__ float sdo[64];

    int bh = blockIdx.x >> 6;
    int c  = blockIdx.x & 63;
    int b  = bh >> 4;
    int h  = bh & 15;
    int tid = threadIdx.x;
    size_t baseC = ((size_t)bh * SEQL + (size_t)c * 64) * HD;
    size_t baseS = ((size_t)bh * NCH + c) * 4096;

    {
        const float4* pC = (const float4*)(g_Cm + baseC);
        const float4* pS = (const float4*)(g_nstates + baseS);
        for (int i4 = tid; i4 < 1024; i4 += 256) {
            int l = i4 >> 4, n4 = (i4 & 15) * 4;
            float4 v = pC[i4];
            sCT[n4][l] = v.x; sCT[n4+1][l] = v.y; sCT[n4+2][l] = v.z; sCT[n4+3][l] = v.w;
            v = pS[i4];
            *(float4*)&sST[l][n4] = v;
        }
    }
    if (tid < 32) {
        float a0 = g_cumA[(size_t)bh * SEQL + c * 64 + 2 * tid];
        float a1 = g_cumA[(size_t)bh * SEQL + c * 64 + 2 * tid + 1];
        scum[2 * tid] = a0; scum[2 * tid + 1] = a1;
        float mx = fmaxf(a0, a1);
#pragma unroll
        for (int o = 16; o; o >>= 1) mx = fmaxf(mx, __shfl_xor_sync(0xffffffffu, mx, o));
        sdo[2 * tid]     = __expf(a0 - mx);
        sdo[2 * tid + 1] = __expf(a1 - mx);
    }
    __syncthreads();

    float nn = g_nnew[bh * NCH + c];
    int tl = (tid >> 4) * 4;
    int tp = (tid & 15) * 4;
    float r[4][4];
#pragma unroll
    for (int a = 0; a < 4; a++)
#pragma unroll
        for (int b2 = 0; b2 < 4; b2++) r[a][b2] = 0.f;
#pragma unroll 4
    for (int n = 0; n < 64; n++) {
        float4 cv = *(const float4*)&sCT[n][tl];
        float4 sv = *(const float4*)&sST[n][tp];
        float cva[4] = {cv.x, cv.y, cv.z, cv.w};
        float sva[4] = {sv.x, sv.y, sv.z, sv.w};
#pragma unroll
        for (int a = 0; a < 4; a++)
#pragma unroll
            for (int b2 = 0; b2 < 4; b2++) r[a][b2] = fmaf(cva[a], sva[b2], r[a][b2]);
    }
#pragma unroll
    for (int a = 0; a < 4; a++) {
        int l = tl + a;
        float d = sdo[l];
        float nm = g_ndiag[(size_t)bh * SEQL + c * 64 + l] + nn * d;
        float inv = 1.f / nm;
        int s = c * 64 + l;
        size_t rowb = ((size_t)b * SEQL + s) * K2 + h * 64;
        const float4 yv = *(const float4*)(g_Ydiag + baseC + (size_t)l * 64 + tp);
        float v0 = (yv.x + d * r[a][0]) * inv;
        float v1 = (yv.y + d * r[a][1]) * inv;
        float v2 = (yv.z + d * r[a][2]) * inv;
        float v3 = (yv.w + d * r[a][3]) * inv;
        __nv_bfloat16 h0 = __float2bfloat16(v0), h1 = __float2bfloat16(v1);
        __nv_bfloat16 h2 = __float2bfloat16(v2), h3 = __float2bfloat16(v3);
        __nv_bfloat16 l0 = __float2bfloat16(v0 - __bfloat162float(h0));
        __nv_bfloat16 l1 = __float2bfloat16(v1 - __bfloat162float(h1));
        __nv_bfloat16 l2 = __float2bfloat16(v2 - __bfloat162float(h2));
        __nv_bfloat16 l3 = __float2bfloat16(v3 - __bfloat162float(h3));
        __nv_bfloat162 hp0 = __halves2bfloat162(h0, h1), hp1 = __halves2bfloat162(h2, h3);
        __nv_bfloat162 lp0 = __halves2bfloat162(l0, l1), lp1 = __halves2bfloat162(l2, l3);
        uint2 hu, lu;
        hu.x = *(uint32_t*)&hp0; hu.y = *(uint32_t*)&hp1;
        lu.x = *(uint32_t*)&lp0; lu.y = *(uint32_t*)&lp1;
        *(uint2*)(g_ys + rowb + tp)          = hu;
        *(uint2*)(g_ys + rowb + tp + DMODEL) = lu;
    }
}

// ------------------------------- launch ---------------------------------------------
extern "C" void kernel_launch(void* const* d_in, const int* in_sizes, int n_in,
                              void* d_out, int out_size)
{
    const float* x   = (const float*)d_in[0];
    const float* ipw = (const float*)d_in[1];
    const float* cw  = (const float*)d_in[2];
    const float* cb  = (const float*)d_in[3];
    const float* wb  = (const float*)d_in[4];
    const float* opw = (const float*)d_in[5];
    float* out = (float*)d_out;

    float *p_xw = nullptr;
    __nv_bfloat16 *p_xs, *p_ws, *p_w2s, *p_ys;
    cudaGetSymbolAddress((void**)&p_xw, g_xw);
    cudaGetSymbolAddress((void**)&p_xs, g_xs);
    cudaGetSymbolAddress((void**)&p_ws, g_ws);
    cudaGetSymbolAddress((void**)&p_w2s, g_w2s);
    cudaGetSymbolAddress((void**)&p_ys, g_ys);

    const int SMEM_CHUNK = 3 * 64 * RP * 4;
    cudaFuncSetAttribute(chunk_k, cudaFuncAttributeMaxDynamicSharedMemorySize, SMEM_CHUNK);
    const int SMEM_GEMM = NSTG * (int)STGB;
    cudaFuncSetAttribute(mma_gemm_k, cudaFuncAttributeMaxDynamicSharedMemorySize, SMEM_GEMM);

    // 0) merged bf16 splits (vectorized)
    {
        int total = NSPLIT_A4 + NSPLIT_B4 + NSPLIT_C4;
        split_all_k<<<(total + 255) / 256, 256>>>(x, ipw, opw);
    }

    // 1) in_proj via HMMA
    {
        dim3 g(NPAD_IP / 128, BSN / 128);
        mma_gemm_k<<<g, 256, SMEM_GEMM>>>(p_xs, p_ws, p_xw, K3, DINP, DINP, 1024, 2048);
    }

    // 2) fused conv + per-chunk tiles
    chunk_k<<<BHN * NCH, 256, SMEM_CHUNK>>>(cw, cb, wb);

    // 3) chunk recurrence scan
    scan_k<<<BHN * 16, 256>>>();

    // 4) off-diagonal + normalize + fused bf16 split
    yoff_k<<<BHN * NCH, 256>>>();

    // 5) out_proj via HMMA
    {
        dim3 g(DMODEL / 128, BSN / 128);
        mma_gemm_k<<<g, 256, SMEM_GEMM>>>(p_ys, p_w2s, out, K3, DMODEL, DMODEL, 1024, 2048);
    }
}